// round 14
// baseline (speedup 1.0000x reference)
#include <cuda_runtime.h>
#include <cuda_fp16.h>
#include <math.h>
#include <mma.h>

using namespace nvcuda;

// Problem constants (fixed by the dataset)
#define N_NODES 50000
#define N_PAD   50048                        // 391 * 128
#define E_EDGES 800000
#define E_TOT   (E_EDGES + N_NODES)
#define SCAN_NB ((N_NODES + 1023) / 1024)   // 49

// ---------------- scratch (static __device__ allocations only) ----------------
__device__ __half g_x16[(size_t)N_PAD * 128];   // fp16 copy of x
__device__ __half g_h1a16[(size_t)N_PAD * 128]; // elu(gat1) fp16 (gemm2 input)
__device__ __half g_h16[(size_t)N_PAD * 256];   // fp16 h (per-layer stride)
__device__ __half g_w1h[128 * 128];
__device__ __half g_w2h[128 * 256];
__device__ float  g_as1[N_NODES * 4];
__device__ float  g_ad1[N_NODES * 4];
__device__ float  g_as2[N_NODES * 8];
__device__ float  g_ad2[N_NODES * 8];
__device__ float  g_m  [N_NODES * 8];           // per-node softmax max
__device__ float  g_is [N_NODES * 8];           // per-node 1/sum
__device__ int    g_cnt[N_NODES];
__device__ int    g_tmp[N_NODES];
__device__ int    g_bsum[SCAN_NB];
__device__ int    g_boff[SCAN_NB];
__device__ int    g_rowptr[N_NODES + 1];
__device__ int    g_cursor[N_NODES];
__device__ int    g_col[E_TOT];
__device__ int    g_is64;

// ---------------- dtype detection for edge_index (int64 vs int32) -------------
__global__ void detect64_kernel(const unsigned int* __restrict__ w) {
    __shared__ int any;
    if (threadIdx.x == 0) any = 0;
    __syncthreads();
    for (int i = 1 + 2 * threadIdx.x; i < 2048; i += 2 * blockDim.x)
        if (w[i] != 0u) any = 1;   // benign race
    __syncthreads();
    if (threadIdx.x == 0) g_is64 = (any == 0) ? 1 : 0;
}

__global__ void zero_cnt_kernel() {
    int i = blockIdx.x * blockDim.x + threadIdx.x;
    if (i < N_NODES) g_cnt[i] = 0;
}

__global__ void count_kernel(const void* __restrict__ ei) {
    int e = blockIdx.x * blockDim.x + threadIdx.x;
    if (e >= E_TOT) return;
    int dst;
    if (e < E_EDGES) {
        if (g_is64) dst = (int)((const long long*)ei)[(size_t)E_EDGES + e];
        else        dst = ((const int*)ei)[E_EDGES + e];
    } else {
        dst = e - E_EDGES;   // self loop
    }
    atomicAdd(&g_cnt[dst], 1);
}

// ---------------- multi-block scan (3 tiny kernels) ---------------------------
__global__ void scan1_kernel() {
    int b = blockIdx.x, tid = threadIdx.x;
    int i = b * 1024 + tid;
    int lane = tid & 31, wid = tid >> 5;
    int v = (i < N_NODES) ? g_cnt[i] : 0;
    int x = v;
#pragma unroll
    for (int off = 1; off < 32; off <<= 1) {
        int t = __shfl_up_sync(0xffffffffu, x, off);
        if (lane >= off) x += t;
    }
    __shared__ int wsum[32];
    if (lane == 31) wsum[wid] = x;
    __syncthreads();
    if (wid == 0) {
        int y = wsum[lane];
#pragma unroll
        for (int off = 1; off < 32; off <<= 1) {
            int t = __shfl_up_sync(0xffffffffu, y, off);
            if (lane >= off) y += t;
        }
        wsum[lane] = y;
    }
    __syncthreads();
    int incl = x + (wid ? wsum[wid - 1] : 0);
    if (i < N_NODES) g_tmp[i] = incl;
    if (tid == 1023) g_bsum[b] = incl;
}

__global__ void scan2_kernel() {
    if (threadIdx.x == 0) {
        int run = 0;
#pragma unroll 1
        for (int j = 0; j < SCAN_NB; j++) { g_boff[j] = run; run += g_bsum[j]; }
        g_rowptr[0] = 0;
    }
}

__global__ void scan3_kernel() {
    int i = blockIdx.x * blockDim.x + threadIdx.x;
    if (i >= N_NODES) return;
    int incl = g_tmp[i] + g_boff[i >> 10];
    g_rowptr[i + 1] = incl;
    g_cursor[i]     = incl - g_cnt[i];
}

__global__ void scatter_kernel(const void* __restrict__ ei) {
    int e = blockIdx.x * blockDim.x + threadIdx.x;
    if (e >= E_TOT) return;
    int src, dst;
    if (e < E_EDGES) {
        if (g_is64) {
            const long long* p = (const long long*)ei;
            src = (int)p[e];
            dst = (int)p[(size_t)E_EDGES + e];
        } else {
            const int* p = (const int*)ei;
            src = p[e];
            dst = p[E_EDGES + e];
        }
    } else {
        src = dst = e - E_EDGES;
    }
    int pos = atomicAdd(&g_cursor[dst], 1);
    g_col[pos] = src;
}

// ---------------- fp32 -> fp16 conversions ------------------------------------
__global__ void convx_kernel(const float* __restrict__ x) {
    int i = blockIdx.x * blockDim.x + threadIdx.x;
    if (i >= N_NODES * 32) return;             // 128/4 float4s per row
    float4 v = ((const float4*)x)[i];
    ((__half2*)g_x16)[2 * i]     = __floats2half2_rn(v.x, v.y);
    ((__half2*)g_x16)[2 * i + 1] = __floats2half2_rn(v.z, v.w);
}

__global__ void convw_kernel(const float* __restrict__ W1,
                             const float* __restrict__ W2) {
    int i = blockIdx.x * blockDim.x + threadIdx.x;
    if (i < 4096) {                             // W1: 16384 floats
        float4 v = ((const float4*)W1)[i];
        ((__half2*)g_w1h)[2 * i]     = __floats2half2_rn(v.x, v.y);
        ((__half2*)g_w1h)[2 * i + 1] = __floats2half2_rn(v.z, v.w);
    } else if (i < 4096 + 8192) {               // W2: 32768 floats
        int j = i - 4096;
        float4 v = ((const float4*)W2)[j];
        ((__half2*)g_w2h)[2 * j]     = __floats2half2_rn(v.x, v.y);
        ((__half2*)g_w2h)[2 * j + 1] = __floats2half2_rn(v.z, v.w);
    }
}

// ------- fp16 tensor-core GEMM with fused alpha + fp16-store epilogue ---------
#define HG_BM 128
#define HG_BN 64
#define HG_BK 32
#define HLDA 40
#define HLDB 72
#define CT_LD 72   // fp32 epilogue tile leading dim

#define SMEM_BYTES (HG_BM * CT_LD * 4)   // 36864 > Ah+Bh bytes (14848)

template <int H>
__global__ void hgemm_fused_kernel(const __half* __restrict__ A,
                                   const __half* __restrict__ Bw,
                                   __half* __restrict__ H16,
                                   float* __restrict__ as_out,
                                   float* __restrict__ ad_out,
                                   const float* __restrict__ att_s,
                                   const float* __restrict__ att_d,
                                   int K) {
    constexpr int N = H * 32;
    __shared__ __align__(16) char smraw[SMEM_BYTES];
    __half* Ah = (__half*)smraw;
    __half* Bh = (__half*)(smraw + HG_BM * HLDA * 2);
    float*  Ct = (float*)smraw;

    int tid = threadIdx.x;
    int wid = tid >> 5;
    int wm = wid & 3, wn = wid >> 2;
    size_t row0 = (size_t)blockIdx.y * HG_BM;
    int col0 = blockIdx.x * HG_BN;

    wmma::fragment<wmma::accumulator, 16, 16, 16, float> c[2][2];
#pragma unroll
    for (int i = 0; i < 2; i++)
#pragma unroll
        for (int j = 0; j < 2; j++) wmma::fill_fragment(c[i][j], 0.f);

    for (int k0 = 0; k0 < K; k0 += HG_BK) {
#pragma unroll
        for (int i = 0; i < 2; i++) {
            int f = tid + i * 256;
            int r = f >> 2, cc = (f & 3) * 8;
            *(uint4*)(Ah + r * HLDA + cc) =
                *(const uint4*)(A + (row0 + r) * K + k0 + cc);
        }
        {
            int r = tid >> 3, cc = (tid & 7) * 8;
            *(uint4*)(Bh + r * HLDB + cc) =
                *(const uint4*)(Bw + (size_t)(k0 + r) * N + col0 + cc);
        }
        __syncthreads();
#pragma unroll
        for (int kk = 0; kk < HG_BK; kk += 16) {
            wmma::fragment<wmma::matrix_a, 16, 16, 16, __half, wmma::row_major> a[2];
            wmma::fragment<wmma::matrix_b, 16, 16, 16, __half, wmma::row_major> b[2];
#pragma unroll
            for (int mi = 0; mi < 2; mi++)
                wmma::load_matrix_sync(a[mi], Ah + (wm * 32 + mi * 16) * HLDA + kk, HLDA);
#pragma unroll
            for (int ni = 0; ni < 2; ni++)
                wmma::load_matrix_sync(b[ni], Bh + kk * HLDB + wn * 32 + ni * 16, HLDB);
#pragma unroll
            for (int mi = 0; mi < 2; mi++)
#pragma unroll
                for (int ni = 0; ni < 2; ni++)
                    wmma::mma_sync(c[mi][ni], a[mi], b[ni], c[mi][ni]);
        }
        __syncthreads();
    }

    // epilogue: spill fp32 tile to smem (operand buffers are dead now)
#pragma unroll
    for (int mi = 0; mi < 2; mi++)
#pragma unroll
        for (int ni = 0; ni < 2; ni++)
            wmma::store_matrix_sync(
                Ct + (wm * 32 + mi * 16) * CT_LD + wn * 32 + ni * 16,
                c[mi][ni], CT_LD, wmma::mem_row_major);
    __syncthreads();

    // each thread owns one (row, 32-col head slice): dots + fp16 store
    int row = tid >> 1;
    int seg = tid & 1;
    size_t node = row0 + row;
    int head = (col0 >> 5) + seg;
    const float* Crow = Ct + row * CT_LD + seg * 32;
    const float* a1 = att_s + head * 32;
    const float* a2 = att_d + head * 32;

    float s1 = 0.f, s2 = 0.f;
    __half hv[32];
#pragma unroll
    for (int j = 0; j < 32; j += 4) {
        float4 v  = *(const float4*)(Crow + j);
        float4 w1 = *(const float4*)(a1 + j);
        float4 w2 = *(const float4*)(a2 + j);
        s1 += v.x * w1.x + v.y * w1.y + v.z * w1.z + v.w * w1.w;
        s2 += v.x * w2.x + v.y * w2.y + v.z * w2.z + v.w * w2.w;
        *(__half2*)(hv + j)     = __floats2half2_rn(v.x, v.y);
        *(__half2*)(hv + j + 2) = __floats2half2_rn(v.z, v.w);
    }
    __half* hp = H16 + node * N + col0 + seg * 32;
#pragma unroll
    for (int j = 0; j < 4; j++)
        ((uint4*)hp)[j] = ((uint4*)hv)[j];
    if (node < N_NODES) {
        as_out[node * H + head] = s1;
        ad_out[node * H + head] = s2;
    }
}

// ------- stats: one warp per destination node, online softmax only ------------
// Writes per-node m[h], inv_s[h]; per-edge weights are reconstructed in agg.
template <int H>
__global__ void stats_kernel(const float* __restrict__ asrc,
                             const float* __restrict__ adst) {
    int w    = (blockIdx.x * blockDim.x + threadIdx.x) >> 5;
    int lane = threadIdx.x & 31;
    if (w >= N_NODES) return;
    int beg = g_rowptr[w], end = g_rowptr[w + 1];

    float ad[H];
#pragma unroll
    for (int h = 0; h < H; h++) ad[h] = adst[(size_t)w * H + h];

    float m[H], s[H];
#pragma unroll
    for (int h = 0; h < H; h++) { m[h] = -1e30f; s[h] = 0.f; }
    for (int e = beg + lane; e < end; e += 32) {
        int src = g_col[e];
        const float4* ap4 = (const float4*)(asrc + (size_t)src * H);
        float av[H];
#pragma unroll
        for (int q = 0; q < H / 4; q++) {
            float4 t = ap4[q];
            av[4 * q] = t.x; av[4 * q + 1] = t.y; av[4 * q + 2] = t.z; av[4 * q + 3] = t.w;
        }
#pragma unroll
        for (int h = 0; h < H; h++) {
            float x = av[h] + ad[h];
            x = x > 0.f ? x : 0.2f * x;
            if (x > m[h]) {
                s[h] = s[h] * __expf(m[h] - x) + 1.f;
                m[h] = x;
            } else {
                s[h] += __expf(x - m[h]);
            }
        }
    }
#pragma unroll
    for (int h = 0; h < H; h++) {
        float mw = m[h];
#pragma unroll
        for (int off = 16; off; off >>= 1)
            mw = fmaxf(mw, __shfl_xor_sync(0xffffffffu, mw, off));
        float sw = s[h] * __expf(m[h] - mw);
#pragma unroll
        for (int off = 16; off; off >>= 1)
            sw += __shfl_xor_sync(0xffffffffu, sw, off);
        m[h] = mw;
        s[h] = 1.f / sw;
    }
    if (lane < H) {
        g_m [(size_t)w * H + lane] = m[lane];
        g_is[(size_t)w * H + lane] = s[lane];
    }
}

// ------- aggregation: one warp per node, inline weights, fp16 gathers ---------
// Layer 1 (H=4, concat+ELU): lane L owns channels 4L..4L+3 of head L/8.
// Weight reconstructed per lane: wt = exp(leaky(asrc+adst) - m) * inv_s.
__global__ void agg1_kernel(const float* __restrict__ asrc,
                            const float* __restrict__ adst,
                            const float* __restrict__ bias) {
    int w    = (blockIdx.x * blockDim.x + threadIdx.x) >> 5;
    int lane = threadIdx.x & 31;
    if (w >= N_NODES) return;
    int beg = g_rowptr[w], end = g_rowptr[w + 1];
    int hsel = lane >> 3;

    float ad_h = adst[(size_t)w * 4 + hsel];
    float m_h  = g_m [(size_t)w * 4 + hsel];
    float is_h = g_is[(size_t)w * 4 + hsel];

    float acc[4] = {0.f, 0.f, 0.f, 0.f};
    for (int e = beg; e < end; e++) {
        int src = g_col[e];
        float x = asrc[(size_t)src * 4 + hsel] + ad_h;    // 1-sector broadcast
        x = x > 0.f ? x : 0.2f * x;
        float wt = __expf(x - m_h) * is_h;
        uint2 hv = *((const uint2*)(g_h16 + (size_t)src * 128) + lane);
        float2 f0 = __half22float2(*(__half2*)&hv.x);
        float2 f1 = __half22float2(*(__half2*)&hv.y);
        acc[0] += f0.x * wt;
        acc[1] += f0.y * wt;
        acc[2] += f1.x * wt;
        acc[3] += f1.y * wt;
    }
    float4 bv = *((const float4*)bias + lane);
    float4 o;
    o.x = acc[0] + bv.x; o.y = acc[1] + bv.y; o.z = acc[2] + bv.z; o.w = acc[3] + bv.w;
    o.x = o.x > 0.f ? o.x : expm1f(o.x);
    o.y = o.y > 0.f ? o.y : expm1f(o.y);
    o.z = o.z > 0.f ? o.z : expm1f(o.z);
    o.w = o.w > 0.f ? o.w : expm1f(o.w);
    uint2 o16;
    *(__half2*)&o16.x = __floats2half2_rn(o.x, o.y);
    *(__half2*)&o16.y = __floats2half2_rn(o.z, o.w);
    ((uint2*)(g_h1a16 + (size_t)w * 128))[lane] = o16;
}

// Layer 2 (H=8, mean over heads): lane L owns channels of head L/4.
__global__ void agg2_kernel(const float* __restrict__ asrc,
                            const float* __restrict__ adst,
                            const float* __restrict__ bias,
                            float* __restrict__ out) {
    int w    = (blockIdx.x * blockDim.x + threadIdx.x) >> 5;
    int lane = threadIdx.x & 31;
    if (w >= N_NODES) return;
    int beg = g_rowptr[w], end = g_rowptr[w + 1];
    int hsel = lane >> 2;

    float ad_h = adst[(size_t)w * 8 + hsel];
    float m_h  = g_m [(size_t)w * 8 + hsel];
    float is_h = g_is[(size_t)w * 8 + hsel];

    float acc[8];
#pragma unroll
    for (int j = 0; j < 8; j++) acc[j] = 0.f;

    for (int e = beg; e < end; e++) {
        int src = g_col[e];
        float x = asrc[(size_t)src * 8 + hsel] + ad_h;    // 1-sector broadcast
        x = x > 0.f ? x : 0.2f * x;
        float wt = __expf(x - m_h) * is_h;
        uint4 hv = *((const uint4*)(g_h16 + (size_t)src * 256) + lane);
        float2 f0 = __half22float2(*(__half2*)&hv.x);
        float2 f1 = __half22float2(*(__half2*)&hv.y);
        float2 f2 = __half22float2(*(__half2*)&hv.z);
        float2 f3 = __half22float2(*(__half2*)&hv.w);
        acc[0] += f0.x * wt; acc[1] += f0.y * wt;
        acc[2] += f1.x * wt; acc[3] += f1.y * wt;
        acc[4] += f2.x * wt; acc[5] += f2.y * wt;
        acc[6] += f3.x * wt; acc[7] += f3.y * wt;
    }
#pragma unroll
    for (int off = 4; off < 32; off <<= 1)
#pragma unroll
        for (int j = 0; j < 8; j++)
            acc[j] += __shfl_xor_sync(0xffffffffu, acc[j], off);

    if (lane < 4) {
        int c0 = lane * 8;
        float4 b0 = *(const float4*)(bias + c0);
        float4 b1 = *(const float4*)(bias + c0 + 4);
        float4 o0, o1;
        o0.x = acc[0] * 0.125f + b0.x; o0.y = acc[1] * 0.125f + b0.y;
        o0.z = acc[2] * 0.125f + b0.z; o0.w = acc[3] * 0.125f + b0.w;
        o1.x = acc[4] * 0.125f + b1.x; o1.y = acc[5] * 0.125f + b1.y;
        o1.z = acc[6] * 0.125f + b1.z; o1.w = acc[7] * 0.125f + b1.w;
        *(float4*)(out + (size_t)w * 32 + c0)     = o0;
        *(float4*)(out + (size_t)w * 32 + c0 + 4) = o1;
    }
}

// ---------------- launch ------------------------------------------------------
extern "C" void kernel_launch(void* const* d_in, const int* in_sizes, int n_in,
                              void* d_out, int out_size) {
    const float* x   = (const float*)d_in[0];
    const void*  ei  = d_in[1];
    const float* W1  = (const float*)d_in[2];
    const float* at_s1 = (const float*)d_in[3];
    const float* at_d1 = (const float*)d_in[4];
    const float* b1  = (const float*)d_in[5];
    const float* W2  = (const float*)d_in[6];
    const float* at_s2 = (const float*)d_in[7];
    const float* at_d2 = (const float*)d_in[8];
    const float* b2  = (const float*)d_in[9];
    float* out = (float*)d_out;

    float *pas1, *pad1, *pas2, *pad2;
    __half *x16, *w1h, *w2h, *h1a16, *h16;
    cudaGetSymbolAddress((void**)&x16, g_x16);
    cudaGetSymbolAddress((void**)&w1h, g_w1h);
    cudaGetSymbolAddress((void**)&w2h, g_w2h);
    cudaGetSymbolAddress((void**)&h1a16, g_h1a16);
    cudaGetSymbolAddress((void**)&h16, g_h16);
    cudaGetSymbolAddress((void**)&pas1, g_as1);
    cudaGetSymbolAddress((void**)&pad1, g_ad1);
    cudaGetSymbolAddress((void**)&pas2, g_as2);
    cudaGetSymbolAddress((void**)&pad2, g_ad2);

    // CSR build + fp16 conversions (conversions independent of CSR)
    detect64_kernel<<<1, 256>>>((const unsigned int*)ei);
    zero_cnt_kernel<<<(N_NODES + 255) / 256, 256>>>();
    count_kernel<<<(E_TOT + 255) / 256, 256>>>(ei);
    convx_kernel<<<(N_NODES * 32 + 255) / 256, 256>>>(x);
    convw_kernel<<<(12288 + 255) / 256, 256>>>(W1, W2);
    scan1_kernel<<<SCAN_NB, 1024>>>();
    scan2_kernel<<<1, 32>>>();
    scan3_kernel<<<(N_NODES + 255) / 256, 256>>>();
    scatter_kernel<<<(E_TOT + 255) / 256, 256>>>(ei);

    dim3 hg1(128 / HG_BN, N_PAD / HG_BM);   // (2, 391)
    dim3 hg2(256 / HG_BN, N_PAD / HG_BM);   // (4, 391)

    // layer 1
    hgemm_fused_kernel<4><<<hg1, 256>>>(x16, w1h, h16, pas1, pad1, at_s1, at_d1, 128);
    stats_kernel<4><<<(N_NODES + 7) / 8, 256>>>(pas1, pad1);
    agg1_kernel<<<(N_NODES + 7) / 8, 256>>>(pas1, pad1, b1);

    // layer 2
    hgemm_fused_kernel<8><<<hg2, 256>>>(h1a16, w2h, h16, pas2, pad2, at_s2, at_d2, 128);
    stats_kernel<8><<<(N_NODES + 7) / 8, 256>>>(pas2, pad2);
    agg2_kernel<<<(N_NODES + 7) / 8, 256>>>(pas2, pad2, b2, out);
}

// round 15
// speedup vs baseline: 1.0435x; 1.0435x over previous
#include <cuda_runtime.h>
#include <cuda_fp16.h>
#include <math.h>
#include <mma.h>

using namespace nvcuda;

// Problem constants (fixed by the dataset)
#define N_NODES 50000
#define N_PAD   50048                        // 391 * 128
#define E_EDGES 800000
#define E_TOT   (E_EDGES + N_NODES)
#define SCAN_NB ((N_NODES + 1023) / 1024)   // 49

// ---------------- scratch (static __device__ allocations only) ----------------
__device__ __half g_x16[(size_t)N_PAD * 128];   // fp16 copy of x
__device__ __half g_h1a16[(size_t)N_PAD * 128]; // elu(gat1) fp16 (gemm2 input)
__device__ __half g_h16[(size_t)N_PAD * 256];   // fp16 h (per-layer stride)
__device__ __half g_w1h[128 * 128];
__device__ __half g_w2h[128 * 256];
__device__ float  g_ew [(size_t)E_TOT * 8];     // per-edge normalized weights
__device__ float  g_as1[N_NODES * 4];
__device__ float  g_ad1[N_NODES * 4];
__device__ float  g_as2[N_NODES * 8];
__device__ float  g_ad2[N_NODES * 8];
__device__ int    g_cnt[N_NODES];
__device__ int    g_tmp[N_NODES];
__device__ int    g_bsum[SCAN_NB];
__device__ int    g_boff[SCAN_NB];
__device__ int    g_rowptr[N_NODES + 1];
__device__ int    g_cursor[N_NODES];
__device__ int    g_col[E_TOT];
__device__ int    g_is64;

// ---------------- dtype detection for edge_index (int64 vs int32) -------------
__global__ void detect64_kernel(const unsigned int* __restrict__ w) {
    __shared__ int any;
    if (threadIdx.x == 0) any = 0;
    __syncthreads();
    for (int i = 1 + 2 * threadIdx.x; i < 2048; i += 2 * blockDim.x)
        if (w[i] != 0u) any = 1;   // benign race
    __syncthreads();
    if (threadIdx.x == 0) g_is64 = (any == 0) ? 1 : 0;
}

__global__ void zero_cnt_kernel() {
    int i = blockIdx.x * blockDim.x + threadIdx.x;
    if (i < N_NODES) g_cnt[i] = 0;
}

__global__ void count_kernel(const void* __restrict__ ei) {
    int e = blockIdx.x * blockDim.x + threadIdx.x;
    if (e >= E_TOT) return;
    int dst;
    if (e < E_EDGES) {
        if (g_is64) dst = (int)((const long long*)ei)[(size_t)E_EDGES + e];
        else        dst = ((const int*)ei)[E_EDGES + e];
    } else {
        dst = e - E_EDGES;   // self loop
    }
    atomicAdd(&g_cnt[dst], 1);
}

// ---------------- multi-block scan (3 tiny kernels) ---------------------------
__global__ void scan1_kernel() {
    int b = blockIdx.x, tid = threadIdx.x;
    int i = b * 1024 + tid;
    int lane = tid & 31, wid = tid >> 5;
    int v = (i < N_NODES) ? g_cnt[i] : 0;
    int x = v;
#pragma unroll
    for (int off = 1; off < 32; off <<= 1) {
        int t = __shfl_up_sync(0xffffffffu, x, off);
        if (lane >= off) x += t;
    }
    __shared__ int wsum[32];
    if (lane == 31) wsum[wid] = x;
    __syncthreads();
    if (wid == 0) {
        int y = wsum[lane];
#pragma unroll
        for (int off = 1; off < 32; off <<= 1) {
            int t = __shfl_up_sync(0xffffffffu, y, off);
            if (lane >= off) y += t;
        }
        wsum[lane] = y;
    }
    __syncthreads();
    int incl = x + (wid ? wsum[wid - 1] : 0);
    if (i < N_NODES) g_tmp[i] = incl;
    if (tid == 1023) g_bsum[b] = incl;
}

__global__ void scan2_kernel() {
    if (threadIdx.x == 0) {
        int run = 0;
#pragma unroll 1
        for (int j = 0; j < SCAN_NB; j++) { g_boff[j] = run; run += g_bsum[j]; }
        g_rowptr[0] = 0;
    }
}

__global__ void scan3_kernel() {
    int i = blockIdx.x * blockDim.x + threadIdx.x;
    if (i >= N_NODES) return;
    int incl = g_tmp[i] + g_boff[i >> 10];
    g_rowptr[i + 1] = incl;
    g_cursor[i]     = incl - g_cnt[i];
}

__global__ void scatter_kernel(const void* __restrict__ ei) {
    int e = blockIdx.x * blockDim.x + threadIdx.x;
    if (e >= E_TOT) return;
    int src, dst;
    if (e < E_EDGES) {
        if (g_is64) {
            const long long* p = (const long long*)ei;
            src = (int)p[e];
            dst = (int)p[(size_t)E_EDGES + e];
        } else {
            const int* p = (const int*)ei;
            src = p[e];
            dst = p[E_EDGES + e];
        }
    } else {
        src = dst = e - E_EDGES;
    }
    int pos = atomicAdd(&g_cursor[dst], 1);
    g_col[pos] = src;
}

// ---------------- fp32 -> fp16 conversions ------------------------------------
__global__ void convx_kernel(const float* __restrict__ x) {
    int i = blockIdx.x * blockDim.x + threadIdx.x;
    if (i >= N_NODES * 32) return;             // 128/4 float4s per row
    float4 v = ((const float4*)x)[i];
    ((__half2*)g_x16)[2 * i]     = __floats2half2_rn(v.x, v.y);
    ((__half2*)g_x16)[2 * i + 1] = __floats2half2_rn(v.z, v.w);
}

__global__ void convw_kernel(const float* __restrict__ W1,
                             const float* __restrict__ W2) {
    int i = blockIdx.x * blockDim.x + threadIdx.x;
    if (i < 4096) {                             // W1: 16384 floats
        float4 v = ((const float4*)W1)[i];
        ((__half2*)g_w1h)[2 * i]     = __floats2half2_rn(v.x, v.y);
        ((__half2*)g_w1h)[2 * i + 1] = __floats2half2_rn(v.z, v.w);
    } else if (i < 4096 + 8192) {               // W2: 32768 floats
        int j = i - 4096;
        float4 v = ((const float4*)W2)[j];
        ((__half2*)g_w2h)[2 * j]     = __floats2half2_rn(v.x, v.y);
        ((__half2*)g_w2h)[2 * j + 1] = __floats2half2_rn(v.z, v.w);
    }
}

// ------- fp16 tensor-core GEMM with fused alpha + fp16-store epilogue ---------
#define HG_BM 128
#define HG_BN 64
#define HG_BK 32
#define HLDA 40
#define HLDB 72
#define CT_LD 72   // fp32 epilogue tile leading dim

#define SMEM_BYTES (HG_BM * CT_LD * 4)   // 36864 > Ah+Bh bytes (14848)

template <int H>
__global__ void hgemm_fused_kernel(const __half* __restrict__ A,
                                   const __half* __restrict__ Bw,
                                   __half* __restrict__ H16,
                                   float* __restrict__ as_out,
                                   float* __restrict__ ad_out,
                                   const float* __restrict__ att_s,
                                   const float* __restrict__ att_d,
                                   int K) {
    constexpr int N = H * 32;
    __shared__ __align__(16) char smraw[SMEM_BYTES];
    __half* Ah = (__half*)smraw;
    __half* Bh = (__half*)(smraw + HG_BM * HLDA * 2);
    float*  Ct = (float*)smraw;

    int tid = threadIdx.x;
    int wid = tid >> 5;
    int wm = wid & 3, wn = wid >> 2;
    size_t row0 = (size_t)blockIdx.y * HG_BM;
    int col0 = blockIdx.x * HG_BN;

    wmma::fragment<wmma::accumulator, 16, 16, 16, float> c[2][2];
#pragma unroll
    for (int i = 0; i < 2; i++)
#pragma unroll
        for (int j = 0; j < 2; j++) wmma::fill_fragment(c[i][j], 0.f);

    for (int k0 = 0; k0 < K; k0 += HG_BK) {
#pragma unroll
        for (int i = 0; i < 2; i++) {
            int f = tid + i * 256;
            int r = f >> 2, cc = (f & 3) * 8;
            *(uint4*)(Ah + r * HLDA + cc) =
                *(const uint4*)(A + (row0 + r) * K + k0 + cc);
        }
        {
            int r = tid >> 3, cc = (tid & 7) * 8;
            *(uint4*)(Bh + r * HLDB + cc) =
                *(const uint4*)(Bw + (size_t)(k0 + r) * N + col0 + cc);
        }
        __syncthreads();
#pragma unroll
        for (int kk = 0; kk < HG_BK; kk += 16) {
            wmma::fragment<wmma::matrix_a, 16, 16, 16, __half, wmma::row_major> a[2];
            wmma::fragment<wmma::matrix_b, 16, 16, 16, __half, wmma::row_major> b[2];
#pragma unroll
            for (int mi = 0; mi < 2; mi++)
                wmma::load_matrix_sync(a[mi], Ah + (wm * 32 + mi * 16) * HLDA + kk, HLDA);
#pragma unroll
            for (int ni = 0; ni < 2; ni++)
                wmma::load_matrix_sync(b[ni], Bh + kk * HLDB + wn * 32 + ni * 16, HLDB);
#pragma unroll
            for (int mi = 0; mi < 2; mi++)
#pragma unroll
                for (int ni = 0; ni < 2; ni++)
                    wmma::mma_sync(c[mi][ni], a[mi], b[ni], c[mi][ni]);
        }
        __syncthreads();
    }

    // epilogue: spill fp32 tile to smem (operand buffers are dead now)
#pragma unroll
    for (int mi = 0; mi < 2; mi++)
#pragma unroll
        for (int ni = 0; ni < 2; ni++)
            wmma::store_matrix_sync(
                Ct + (wm * 32 + mi * 16) * CT_LD + wn * 32 + ni * 16,
                c[mi][ni], CT_LD, wmma::mem_row_major);
    __syncthreads();

    // each thread owns one (row, 32-col head slice): dots + fp16 store
    int row = tid >> 1;
    int seg = tid & 1;
    size_t node = row0 + row;
    int head = (col0 >> 5) + seg;
    const float* Crow = Ct + row * CT_LD + seg * 32;
    const float* a1 = att_s + head * 32;
    const float* a2 = att_d + head * 32;

    float s1 = 0.f, s2 = 0.f;
    __half hv[32];
#pragma unroll
    for (int j = 0; j < 32; j += 4) {
        float4 v  = *(const float4*)(Crow + j);
        float4 w1 = *(const float4*)(a1 + j);
        float4 w2 = *(const float4*)(a2 + j);
        s1 += v.x * w1.x + v.y * w1.y + v.z * w1.z + v.w * w1.w;
        s2 += v.x * w2.x + v.y * w2.y + v.z * w2.z + v.w * w2.w;
        *(__half2*)(hv + j)     = __floats2half2_rn(v.x, v.y);
        *(__half2*)(hv + j + 2) = __floats2half2_rn(v.z, v.w);
    }
    __half* hp = H16 + node * N + col0 + seg * 32;
#pragma unroll
    for (int j = 0; j < 4; j++)
        ((uint4*)hp)[j] = ((uint4*)hv)[j];
    if (node < N_NODES) {
        as_out[node * H + head] = s1;
        ad_out[node * H + head] = s2;
    }
}

// ------- stats + per-edge weight precompute (R13 measured-good form) ----------
template <int H>
__global__ void stats_kernel(const float* __restrict__ asrc,
                             const float* __restrict__ adst) {
    int w    = (blockIdx.x * blockDim.x + threadIdx.x) >> 5;
    int lane = threadIdx.x & 31;
    if (w >= N_NODES) return;
    int beg = g_rowptr[w], end = g_rowptr[w + 1];

    float ad[H];
#pragma unroll
    for (int h = 0; h < H; h++) ad[h] = adst[(size_t)w * H + h];

    float m[H], s[H];
#pragma unroll
    for (int h = 0; h < H; h++) { m[h] = -1e30f; s[h] = 0.f; }
    for (int e = beg + lane; e < end; e += 32) {
        int src = g_col[e];
        const float4* ap4 = (const float4*)(asrc + (size_t)src * H);
        float av[H];
#pragma unroll
        for (int q = 0; q < H / 4; q++) {
            float4 t = ap4[q];
            av[4 * q] = t.x; av[4 * q + 1] = t.y; av[4 * q + 2] = t.z; av[4 * q + 3] = t.w;
        }
#pragma unroll
        for (int h = 0; h < H; h++) {
            float x = av[h] + ad[h];
            x = x > 0.f ? x : 0.2f * x;
            if (x > m[h]) {
                s[h] = s[h] * __expf(m[h] - x) + 1.f;
                m[h] = x;
            } else {
                s[h] += __expf(x - m[h]);
            }
        }
    }
#pragma unroll
    for (int h = 0; h < H; h++) {
        float mw = m[h];
#pragma unroll
        for (int off = 16; off; off >>= 1)
            mw = fmaxf(mw, __shfl_xor_sync(0xffffffffu, mw, off));
        float sw = s[h] * __expf(m[h] - mw);
#pragma unroll
        for (int off = 16; off; off >>= 1)
            sw += __shfl_xor_sync(0xffffffffu, sw, off);
        m[h] = mw;
        s[h] = 1.f / sw;     // inv_s
    }

    // weight sweep: lane-parallel, coalesced float4 stores
    for (int e = beg + lane; e < end; e += 32) {
        int src = g_col[e];
        const float4* ap4 = (const float4*)(asrc + (size_t)src * H);
        float av[H], wv[H];
#pragma unroll
        for (int q = 0; q < H / 4; q++) {
            float4 t = ap4[q];
            av[4 * q] = t.x; av[4 * q + 1] = t.y; av[4 * q + 2] = t.z; av[4 * q + 3] = t.w;
        }
#pragma unroll
        for (int h = 0; h < H; h++) {
            float x = av[h] + ad[h];
            x = x > 0.f ? x : 0.2f * x;
            wv[h] = __expf(x - m[h]) * s[h];
        }
        float4* wp = (float4*)(g_ew + (size_t)e * H);
#pragma unroll
        for (int q = 0; q < H / 4; q++)
            wp[q] = make_float4(wv[4 * q], wv[4 * q + 1], wv[4 * q + 2], wv[4 * q + 3]);
    }
}

// ------- aggregation: one warp per node, unroll-4 edge walk for MLP -----------
// Layer 1 (H=4, concat+ELU): writes fp16 h1a directly (gemm2 input).
__global__ void agg1_kernel(const float* __restrict__ bias) {
    int w    = (blockIdx.x * blockDim.x + threadIdx.x) >> 5;
    int lane = threadIdx.x & 31;
    if (w >= N_NODES) return;
    int beg = g_rowptr[w], end = g_rowptr[w + 1];
    int hsel = lane >> 3;

    float acc[4] = {0.f, 0.f, 0.f, 0.f};
    int e = beg;
    for (; e + 4 <= end; e += 4) {
        int s0 = g_col[e], s1 = g_col[e + 1], s2 = g_col[e + 2], s3 = g_col[e + 3];
        float w0 = g_ew[(size_t)(e    ) * 4 + hsel];
        float w1 = g_ew[(size_t)(e + 1) * 4 + hsel];
        float w2 = g_ew[(size_t)(e + 2) * 4 + hsel];
        float w3 = g_ew[(size_t)(e + 3) * 4 + hsel];
        uint2 v0 = *((const uint2*)(g_h16 + (size_t)s0 * 128) + lane);
        uint2 v1 = *((const uint2*)(g_h16 + (size_t)s1 * 128) + lane);
        uint2 v2 = *((const uint2*)(g_h16 + (size_t)s2 * 128) + lane);
        uint2 v3 = *((const uint2*)(g_h16 + (size_t)s3 * 128) + lane);
        float2 a0 = __half22float2(*(__half2*)&v0.x), b0 = __half22float2(*(__half2*)&v0.y);
        float2 a1 = __half22float2(*(__half2*)&v1.x), b1 = __half22float2(*(__half2*)&v1.y);
        float2 a2 = __half22float2(*(__half2*)&v2.x), b2 = __half22float2(*(__half2*)&v2.y);
        float2 a3 = __half22float2(*(__half2*)&v3.x), b3 = __half22float2(*(__half2*)&v3.y);
        acc[0] += a0.x * w0 + a1.x * w1 + a2.x * w2 + a3.x * w3;
        acc[1] += a0.y * w0 + a1.y * w1 + a2.y * w2 + a3.y * w3;
        acc[2] += b0.x * w0 + b1.x * w1 + b2.x * w2 + b3.x * w3;
        acc[3] += b0.y * w0 + b1.y * w1 + b2.y * w2 + b3.y * w3;
    }
    for (; e < end; e++) {
        int src = g_col[e];
        float wt = g_ew[(size_t)e * 4 + hsel];
        uint2 hv = *((const uint2*)(g_h16 + (size_t)src * 128) + lane);
        float2 f0 = __half22float2(*(__half2*)&hv.x);
        float2 f1 = __half22float2(*(__half2*)&hv.y);
        acc[0] += f0.x * wt;
        acc[1] += f0.y * wt;
        acc[2] += f1.x * wt;
        acc[3] += f1.y * wt;
    }
    float4 bv = *((const float4*)bias + lane);
    float4 o;
    o.x = acc[0] + bv.x; o.y = acc[1] + bv.y; o.z = acc[2] + bv.z; o.w = acc[3] + bv.w;
    o.x = o.x > 0.f ? o.x : expm1f(o.x);
    o.y = o.y > 0.f ? o.y : expm1f(o.y);
    o.z = o.z > 0.f ? o.z : expm1f(o.z);
    o.w = o.w > 0.f ? o.w : expm1f(o.w);
    uint2 o16;
    *(__half2*)&o16.x = __floats2half2_rn(o.x, o.y);
    *(__half2*)&o16.y = __floats2half2_rn(o.z, o.w);
    ((uint2*)(g_h1a16 + (size_t)w * 128))[lane] = o16;
}

// Layer 2 (H=8, mean over heads): unroll-2 (uint4 regs are heavier).
__global__ void agg2_kernel(const float* __restrict__ bias,
                            float* __restrict__ out) {
    int w    = (blockIdx.x * blockDim.x + threadIdx.x) >> 5;
    int lane = threadIdx.x & 31;
    if (w >= N_NODES) return;
    int beg = g_rowptr[w], end = g_rowptr[w + 1];
    int hsel = lane >> 2;

    float acc[8];
#pragma unroll
    for (int j = 0; j < 8; j++) acc[j] = 0.f;

    int e = beg;
    for (; e + 2 <= end; e += 2) {
        int s0 = g_col[e], s1 = g_col[e + 1];
        float w0 = g_ew[(size_t)(e    ) * 8 + hsel];
        float w1 = g_ew[(size_t)(e + 1) * 8 + hsel];
        uint4 v0 = *((const uint4*)(g_h16 + (size_t)s0 * 256) + lane);
        uint4 v1 = *((const uint4*)(g_h16 + (size_t)s1 * 256) + lane);
        float2 p0 = __half22float2(*(__half2*)&v0.x), p1 = __half22float2(*(__half2*)&v0.y);
        float2 p2 = __half22float2(*(__half2*)&v0.z), p3 = __half22float2(*(__half2*)&v0.w);
        float2 q0 = __half22float2(*(__half2*)&v1.x), q1 = __half22float2(*(__half2*)&v1.y);
        float2 q2 = __half22float2(*(__half2*)&v1.z), q3 = __half22float2(*(__half2*)&v1.w);
        acc[0] += p0.x * w0 + q0.x * w1;
        acc[1] += p0.y * w0 + q0.y * w1;
        acc[2] += p1.x * w0 + q1.x * w1;
        acc[3] += p1.y * w0 + q1.y * w1;
        acc[4] += p2.x * w0 + q2.x * w1;
        acc[5] += p2.y * w0 + q2.y * w1;
        acc[6] += p3.x * w0 + q3.x * w1;
        acc[7] += p3.y * w0 + q3.y * w1;
    }
    for (; e < end; e++) {
        int src = g_col[e];
        float wt = g_ew[(size_t)e * 8 + hsel];
        uint4 hv = *((const uint4*)(g_h16 + (size_t)src * 256) + lane);
        float2 f0 = __half22float2(*(__half2*)&hv.x);
        float2 f1 = __half22float2(*(__half2*)&hv.y);
        float2 f2 = __half22float2(*(__half2*)&hv.z);
        float2 f3 = __half22float2(*(__half2*)&hv.w);
        acc[0] += f0.x * wt; acc[1] += f0.y * wt;
        acc[2] += f1.x * wt; acc[3] += f1.y * wt;
        acc[4] += f2.x * wt; acc[5] += f2.y * wt;
        acc[6] += f3.x * wt; acc[7] += f3.y * wt;
    }
#pragma unroll
    for (int off = 4; off < 32; off <<= 1)
#pragma unroll
        for (int j = 0; j < 8; j++)
            acc[j] += __shfl_xor_sync(0xffffffffu, acc[j], off);

    if (lane < 4) {
        int c0 = lane * 8;
        float4 b0 = *(const float4*)(bias + c0);
        float4 b1 = *(const float4*)(bias + c0 + 4);
        float4 o0, o1;
        o0.x = acc[0] * 0.125f + b0.x; o0.y = acc[1] * 0.125f + b0.y;
        o0.z = acc[2] * 0.125f + b0.z; o0.w = acc[3] * 0.125f + b0.w;
        o1.x = acc[4] * 0.125f + b1.x; o1.y = acc[5] * 0.125f + b1.y;
        o1.z = acc[6] * 0.125f + b1.z; o1.w = acc[7] * 0.125f + b1.w;
        *(float4*)(out + (size_t)w * 32 + c0)     = o0;
        *(float4*)(out + (size_t)w * 32 + c0 + 4) = o1;
    }
}

// ---------------- launch ------------------------------------------------------
extern "C" void kernel_launch(void* const* d_in, const int* in_sizes, int n_in,
                              void* d_out, int out_size) {
    const float* x   = (const float*)d_in[0];
    const void*  ei  = d_in[1];
    const float* W1  = (const float*)d_in[2];
    const float* at_s1 = (const float*)d_in[3];
    const float* at_d1 = (const float*)d_in[4];
    const float* b1  = (const float*)d_in[5];
    const float* W2  = (const float*)d_in[6];
    const float* at_s2 = (const float*)d_in[7];
    const float* at_d2 = (const float*)d_in[8];
    const float* b2  = (const float*)d_in[9];
    float* out = (float*)d_out;

    float *pas1, *pad1, *pas2, *pad2;
    __half *x16, *w1h, *w2h, *h1a16, *h16;
    cudaGetSymbolAddress((void**)&x16, g_x16);
    cudaGetSymbolAddress((void**)&w1h, g_w1h);
    cudaGetSymbolAddress((void**)&w2h, g_w2h);
    cudaGetSymbolAddress((void**)&h1a16, g_h1a16);
    cudaGetSymbolAddress((void**)&h16, g_h16);
    cudaGetSymbolAddress((void**)&pas1, g_as1);
    cudaGetSymbolAddress((void**)&pad1, g_ad1);
    cudaGetSymbolAddress((void**)&pas2, g_as2);
    cudaGetSymbolAddress((void**)&pad2, g_ad2);

    // CSR build + fp16 conversions (conversions independent of CSR)
    detect64_kernel<<<1, 256>>>((const unsigned int*)ei);
    zero_cnt_kernel<<<(N_NODES + 255) / 256, 256>>>();
    count_kernel<<<(E_TOT + 255) / 256, 256>>>(ei);
    convx_kernel<<<(N_NODES * 32 + 255) / 256, 256>>>(x);
    convw_kernel<<<(12288 + 255) / 256, 256>>>(W1, W2);
    scan1_kernel<<<SCAN_NB, 1024>>>();
    scan2_kernel<<<1, 32>>>();
    scan3_kernel<<<(N_NODES + 255) / 256, 256>>>();
    scatter_kernel<<<(E_TOT + 255) / 256, 256>>>(ei);

    dim3 hg1(128 / HG_BN, N_PAD / HG_BM);   // (2, 391)
    dim3 hg2(256 / HG_BN, N_PAD / HG_BM);   // (4, 391)

    // layer 1
    hgemm_fused_kernel<4><<<hg1, 256>>>(x16, w1h, h16, pas1, pad1, at_s1, at_d1, 128);
    stats_kernel<4><<<(N_NODES + 7) / 8, 256>>>(pas1, pad1);
    agg1_kernel<<<(N_NODES + 7) / 8, 256>>>(b1);

    // layer 2
    hgemm_fused_kernel<8><<<hg2, 256>>>(h1a16, w2h, h16, pas2, pad2, at_s2, at_d2, 128);
    stats_kernel<8><<<(N_NODES + 7) / 8, 256>>>(pas2, pad2);
    agg2_kernel<<<(N_NODES + 7) / 8, 256>>>(b2, out);
}

// round 16
// speedup vs baseline: 1.0465x; 1.0029x over previous
#include <cuda_runtime.h>
#include <cuda_fp16.h>
#include <math.h>
#include <mma.h>

using namespace nvcuda;

// Problem constants (fixed by the dataset)
#define N_NODES 50000
#define N_PAD   50048                        // 391 * 128
#define E_EDGES 800000
#define E_TOT   (E_EDGES + N_NODES)
#define SCAN_NB ((N_NODES + 1023) / 1024)   // 49

// ---------------- scratch (static __device__ allocations only) ----------------
__device__ __half g_x16[(size_t)N_PAD * 128];   // fp16 copy of x
__device__ __half g_h1a16[(size_t)N_PAD * 128]; // elu(gat1) fp16 (gemm2 input)
__device__ __half g_h16[(size_t)N_PAD * 256];   // fp16 h (per-layer stride)
__device__ __half g_w1h[128 * 128];
__device__ __half g_w2h[128 * 256];
__device__ float  g_as1[N_NODES * 4];
__device__ float  g_ad1[N_NODES * 4];
__device__ float  g_as2[N_NODES * 8];
__device__ float  g_ad2[N_NODES * 8];
__device__ int    g_cnt[N_NODES];
__device__ int    g_tmp[N_NODES];
__device__ int    g_bsum[SCAN_NB];
__device__ int    g_boff[SCAN_NB];
__device__ int    g_rowptr[N_NODES + 1];
__device__ int    g_cursor[N_NODES];
__device__ int    g_col[E_TOT];
__device__ int    g_is64;

// ---------------- dtype detection for edge_index (int64 vs int32) -------------
__global__ void detect64_kernel(const unsigned int* __restrict__ w) {
    __shared__ int any;
    if (threadIdx.x == 0) any = 0;
    __syncthreads();
    for (int i = 1 + 2 * threadIdx.x; i < 2048; i += 2 * blockDim.x)
        if (w[i] != 0u) any = 1;   // benign race
    __syncthreads();
    if (threadIdx.x == 0) g_is64 = (any == 0) ? 1 : 0;
}

__global__ void zero_cnt_kernel() {
    int i = blockIdx.x * blockDim.x + threadIdx.x;
    if (i < N_NODES) g_cnt[i] = 0;
}

__global__ void count_kernel(const void* __restrict__ ei) {
    int e = blockIdx.x * blockDim.x + threadIdx.x;
    if (e >= E_TOT) return;
    int dst;
    if (e < E_EDGES) {
        if (g_is64) dst = (int)((const long long*)ei)[(size_t)E_EDGES + e];
        else        dst = ((const int*)ei)[E_EDGES + e];
    } else {
        dst = e - E_EDGES;   // self loop
    }
    atomicAdd(&g_cnt[dst], 1);
}

// ---------------- multi-block scan (3 tiny kernels) ---------------------------
__global__ void scan1_kernel() {
    int b = blockIdx.x, tid = threadIdx.x;
    int i = b * 1024 + tid;
    int lane = tid & 31, wid = tid >> 5;
    int v = (i < N_NODES) ? g_cnt[i] : 0;
    int x = v;
#pragma unroll
    for (int off = 1; off < 32; off <<= 1) {
        int t = __shfl_up_sync(0xffffffffu, x, off);
        if (lane >= off) x += t;
    }
    __shared__ int wsum[32];
    if (lane == 31) wsum[wid] = x;
    __syncthreads();
    if (wid == 0) {
        int y = wsum[lane];
#pragma unroll
        for (int off = 1; off < 32; off <<= 1) {
            int t = __shfl_up_sync(0xffffffffu, y, off);
            if (lane >= off) y += t;
        }
        wsum[lane] = y;
    }
    __syncthreads();
    int incl = x + (wid ? wsum[wid - 1] : 0);
    if (i < N_NODES) g_tmp[i] = incl;
    if (tid == 1023) g_bsum[b] = incl;
}

__global__ void scan2_kernel() {
    if (threadIdx.x == 0) {
        int run = 0;
#pragma unroll 1
        for (int j = 0; j < SCAN_NB; j++) { g_boff[j] = run; run += g_bsum[j]; }
        g_rowptr[0] = 0;
    }
}

__global__ void scan3_kernel() {
    int i = blockIdx.x * blockDim.x + threadIdx.x;
    if (i >= N_NODES) return;
    int incl = g_tmp[i] + g_boff[i >> 10];
    g_rowptr[i + 1] = incl;
    g_cursor[i]     = incl - g_cnt[i];
}

__global__ void scatter_kernel(const void* __restrict__ ei) {
    int e = blockIdx.x * blockDim.x + threadIdx.x;
    if (e >= E_TOT) return;
    int src, dst;
    if (e < E_EDGES) {
        if (g_is64) {
            const long long* p = (const long long*)ei;
            src = (int)p[e];
            dst = (int)p[(size_t)E_EDGES + e];
        } else {
            const int* p = (const int*)ei;
            src = p[e];
            dst = p[E_EDGES + e];
        }
    } else {
        src = dst = e - E_EDGES;
    }
    int pos = atomicAdd(&g_cursor[dst], 1);
    g_col[pos] = src;
}

// ---------------- fp32 -> fp16 conversions ------------------------------------
__global__ void convx_kernel(const float* __restrict__ x) {
    int i = blockIdx.x * blockDim.x + threadIdx.x;
    if (i >= N_NODES * 32) return;             // 128/4 float4s per row
    float4 v = ((const float4*)x)[i];
    ((__half2*)g_x16)[2 * i]     = __floats2half2_rn(v.x, v.y);
    ((__half2*)g_x16)[2 * i + 1] = __floats2half2_rn(v.z, v.w);
}

__global__ void convw_kernel(const float* __restrict__ W1,
                             const float* __restrict__ W2) {
    int i = blockIdx.x * blockDim.x + threadIdx.x;
    if (i < 4096) {                             // W1: 16384 floats
        float4 v = ((const float4*)W1)[i];
        ((__half2*)g_w1h)[2 * i]     = __floats2half2_rn(v.x, v.y);
        ((__half2*)g_w1h)[2 * i + 1] = __floats2half2_rn(v.z, v.w);
    } else if (i < 4096 + 8192) {               // W2: 32768 floats
        int j = i - 4096;
        float4 v = ((const float4*)W2)[j];
        ((__half2*)g_w2h)[2 * j]     = __floats2half2_rn(v.x, v.y);
        ((__half2*)g_w2h)[2 * j + 1] = __floats2half2_rn(v.z, v.w);
    }
}

// ------- fp16 tensor-core GEMM with fused alpha + fp16-store epilogue ---------
#define HG_BM 128
#define HG_BN 64
#define HG_BK 32
#define HLDA 40
#define HLDB 72
#define CT_LD 72   // fp32 epilogue tile leading dim

#define SMEM_BYTES (HG_BM * CT_LD * 4)   // 36864 > Ah+Bh bytes (14848)

template <int H>
__global__ void hgemm_fused_kernel(const __half* __restrict__ A,
                                   const __half* __restrict__ Bw,
                                   __half* __restrict__ H16,
                                   float* __restrict__ as_out,
                                   float* __restrict__ ad_out,
                                   const float* __restrict__ att_s,
                                   const float* __restrict__ att_d,
                                   int K) {
    constexpr int N = H * 32;
    __shared__ __align__(16) char smraw[SMEM_BYTES];
    __half* Ah = (__half*)smraw;
    __half* Bh = (__half*)(smraw + HG_BM * HLDA * 2);
    float*  Ct = (float*)smraw;

    int tid = threadIdx.x;
    int wid = tid >> 5;
    int wm = wid & 3, wn = wid >> 2;
    size_t row0 = (size_t)blockIdx.y * HG_BM;
    int col0 = blockIdx.x * HG_BN;

    wmma::fragment<wmma::accumulator, 16, 16, 16, float> c[2][2];
#pragma unroll
    for (int i = 0; i < 2; i++)
#pragma unroll
        for (int j = 0; j < 2; j++) wmma::fill_fragment(c[i][j], 0.f);

    for (int k0 = 0; k0 < K; k0 += HG_BK) {
#pragma unroll
        for (int i = 0; i < 2; i++) {
            int f = tid + i * 256;
            int r = f >> 2, cc = (f & 3) * 8;
            *(uint4*)(Ah + r * HLDA + cc) =
                *(const uint4*)(A + (row0 + r) * K + k0 + cc);
        }
        {
            int r = tid >> 3, cc = (tid & 7) * 8;
            *(uint4*)(Bh + r * HLDB + cc) =
                *(const uint4*)(Bw + (size_t)(k0 + r) * N + col0 + cc);
        }
        __syncthreads();
#pragma unroll
        for (int kk = 0; kk < HG_BK; kk += 16) {
            wmma::fragment<wmma::matrix_a, 16, 16, 16, __half, wmma::row_major> a[2];
            wmma::fragment<wmma::matrix_b, 16, 16, 16, __half, wmma::row_major> b[2];
#pragma unroll
            for (int mi = 0; mi < 2; mi++)
                wmma::load_matrix_sync(a[mi], Ah + (wm * 32 + mi * 16) * HLDA + kk, HLDA);
#pragma unroll
            for (int ni = 0; ni < 2; ni++)
                wmma::load_matrix_sync(b[ni], Bh + kk * HLDB + wn * 32 + ni * 16, HLDB);
#pragma unroll
            for (int mi = 0; mi < 2; mi++)
#pragma unroll
                for (int ni = 0; ni < 2; ni++)
                    wmma::mma_sync(c[mi][ni], a[mi], b[ni], c[mi][ni]);
        }
        __syncthreads();
    }

    // epilogue: spill fp32 tile to smem (operand buffers are dead now)
#pragma unroll
    for (int mi = 0; mi < 2; mi++)
#pragma unroll
        for (int ni = 0; ni < 2; ni++)
            wmma::store_matrix_sync(
                Ct + (wm * 32 + mi * 16) * CT_LD + wn * 32 + ni * 16,
                c[mi][ni], CT_LD, wmma::mem_row_major);
    __syncthreads();

    // each thread owns one (row, 32-col head slice): dots + fp16 store
    int row = tid >> 1;
    int seg = tid & 1;
    size_t node = row0 + row;
    int head = (col0 >> 5) + seg;
    const float* Crow = Ct + row * CT_LD + seg * 32;
    const float* a1 = att_s + head * 32;
    const float* a2 = att_d + head * 32;

    float s1 = 0.f, s2 = 0.f;
    __half hv[32];
#pragma unroll
    for (int j = 0; j < 32; j += 4) {
        float4 v  = *(const float4*)(Crow + j);
        float4 w1 = *(const float4*)(a1 + j);
        float4 w2 = *(const float4*)(a2 + j);
        s1 += v.x * w1.x + v.y * w1.y + v.z * w1.z + v.w * w1.w;
        s2 += v.x * w2.x + v.y * w2.y + v.z * w2.z + v.w * w2.w;
        *(__half2*)(hv + j)     = __floats2half2_rn(v.x, v.y);
        *(__half2*)(hv + j + 2) = __floats2half2_rn(v.z, v.w);
    }
    __half* hp = H16 + node * N + col0 + seg * 32;
#pragma unroll
    for (int j = 0; j < 4; j++)
        ((uint4*)hp)[j] = ((uint4*)hv)[j];
    if (node < N_NODES) {
        as_out[node * H + head] = s1;
        ad_out[node * H + head] = s2;
    }
}

// ------- fused stats + aggregation: one warp per destination node -------------
// Pass A: lane-parallel online softmax -> m[h], inv_s[h] in registers.
// Pass B: chunks of 32 edges. Each lane computes ALL H weights of one edge
// (scattered asrc gather at MLP=32, exp lane-parallel), stages them in
// warp-private smem; the accumulate loop reads wsm[i*H+hsel] via LDS
// broadcast and src_i via register shuffle. No per-edge weight array in HBM.
template <int H, bool ELU_FP16_OUT>
__global__ void gat_fused_kernel(const float* __restrict__ asrc,
                                 const float* __restrict__ adst,
                                 const float* __restrict__ bias,
                                 float* __restrict__ out_f32) {
    __shared__ float wsm_all[8][32 * H];     // 8 warps/block
    int wslot = threadIdx.x >> 5;
    float* wsm = wsm_all[wslot];

    int w    = (blockIdx.x * blockDim.x + threadIdx.x) >> 5;
    int lane = threadIdx.x & 31;
    if (w >= N_NODES) return;
    int beg = g_rowptr[w], end = g_rowptr[w + 1];

    float ad[H];
#pragma unroll
    for (int h = 0; h < H; h++) ad[h] = adst[(size_t)w * H + h];

    // ---- pass A: online max+sum, lane-parallel ----
    float m[H], s[H];
#pragma unroll
    for (int h = 0; h < H; h++) { m[h] = -1e30f; s[h] = 0.f; }
    for (int e = beg + lane; e < end; e += 32) {
        int src = g_col[e];
        const float4* ap4 = (const float4*)(asrc + (size_t)src * H);
        float av[H];
#pragma unroll
        for (int q = 0; q < H / 4; q++) {
            float4 t = ap4[q];
            av[4 * q] = t.x; av[4 * q + 1] = t.y; av[4 * q + 2] = t.z; av[4 * q + 3] = t.w;
        }
#pragma unroll
        for (int h = 0; h < H; h++) {
            float x = av[h] + ad[h];
            x = x > 0.f ? x : 0.2f * x;
            if (x > m[h]) {
                s[h] = s[h] * __expf(m[h] - x) + 1.f;
                m[h] = x;
            } else {
                s[h] += __expf(x - m[h]);
            }
        }
    }
#pragma unroll
    for (int h = 0; h < H; h++) {
        float mw = m[h];
#pragma unroll
        for (int off = 16; off; off >>= 1)
            mw = fmaxf(mw, __shfl_xor_sync(0xffffffffu, mw, off));
        float sw = s[h] * __expf(m[h] - mw);
#pragma unroll
        for (int off = 16; off; off >>= 1)
            sw += __shfl_xor_sync(0xffffffffu, sw, off);
        m[h] = mw;
        s[h] = 1.f / sw;     // inv_s
    }

    // ---- pass B: chunked weight staging + accumulate ----
    constexpr int CH = (H == 4) ? 4 : 8;     // channels per lane
    int hsel = (H == 4) ? (lane >> 3) : (lane >> 2);
    float acc[CH];
#pragma unroll
    for (int j = 0; j < CH; j++) acc[j] = 0.f;

    for (int c0 = beg; c0 < end; c0 += 32) {
        int ne = min(32, end - c0);
        int mysrc = 0;
        if (lane < ne) {
            int e = c0 + lane;
            mysrc = g_col[e];                 // coalesced
            const float4* ap4 = (const float4*)(asrc + (size_t)mysrc * H);
            float av[H];
#pragma unroll
            for (int q = 0; q < H / 4; q++) {
                float4 t = ap4[q];
                av[4 * q] = t.x; av[4 * q + 1] = t.y; av[4 * q + 2] = t.z; av[4 * q + 3] = t.w;
            }
#pragma unroll
            for (int h = 0; h < H; h++) {
                float x = av[h] + ad[h];
                x = x > 0.f ? x : 0.2f * x;
                wsm[lane * H + h] = __expf(x - m[h]) * s[h];
            }
        }
        __syncwarp();
        for (int i = 0; i < ne; i++) {
            int src_i = __shfl_sync(0xffffffffu, mysrc, i);
            float wt = wsm[i * H + hsel];     // LDS broadcast within head group
            if (H == 4) {
                uint2 hv = *((const uint2*)(g_h16 + (size_t)src_i * 128) + lane);
                float2 f0 = __half22float2(*(__half2*)&hv.x);
                float2 f1 = __half22float2(*(__half2*)&hv.y);
                acc[0] += f0.x * wt;
                acc[1] += f0.y * wt;
                acc[2] += f1.x * wt;
                acc[3] += f1.y * wt;
            } else {
                uint4 hv = *((const uint4*)(g_h16 + (size_t)src_i * 256) + lane);
                float2 f0 = __half22float2(*(__half2*)&hv.x);
                float2 f1 = __half22float2(*(__half2*)&hv.y);
                float2 f2 = __half22float2(*(__half2*)&hv.z);
                float2 f3 = __half22float2(*(__half2*)&hv.w);
                acc[0] += f0.x * wt; acc[1] += f0.y * wt;
                acc[2] += f1.x * wt; acc[3] += f1.y * wt;
                acc[4] += f2.x * wt; acc[5] += f2.y * wt;
                acc[6] += f3.x * wt; acc[7] += f3.y * wt;
            }
        }
        __syncwarp();
    }

    if (ELU_FP16_OUT) {
        // layer 1: concat + bias + ELU, fp16 store to g_h1a16
        float4 bv = *((const float4*)bias + lane);
        float4 o;
        o.x = acc[0] + bv.x; o.y = acc[1] + bv.y; o.z = acc[2] + bv.z; o.w = acc[3] + bv.w;
        o.x = o.x > 0.f ? o.x : expm1f(o.x);
        o.y = o.y > 0.f ? o.y : expm1f(o.y);
        o.z = o.z > 0.f ? o.z : expm1f(o.z);
        o.w = o.w > 0.f ? o.w : expm1f(o.w);
        uint2 o16;
        *(__half2*)&o16.x = __floats2half2_rn(o.x, o.y);
        *(__half2*)&o16.y = __floats2half2_rn(o.z, o.w);
        ((uint2*)(g_h1a16 + (size_t)w * 128))[lane] = o16;
    } else {
        // layer 2: head-mean + bias, fp32 store to out
#pragma unroll
        for (int off = 4; off < 32; off <<= 1)
#pragma unroll
            for (int j = 0; j < CH; j++)
                acc[j] += __shfl_xor_sync(0xffffffffu, acc[j], off);
        if (lane < 4) {
            int c0 = lane * 8;
            float4 b0 = *(const float4*)(bias + c0);
            float4 b1 = *(const float4*)(bias + c0 + 4);
            float4 o0, o1;
            o0.x = acc[0] * 0.125f + b0.x; o0.y = acc[1] * 0.125f + b0.y;
            o0.z = acc[2] * 0.125f + b0.z; o0.w = acc[3] * 0.125f + b0.w;
            o1.x = acc[4] * 0.125f + b1.x; o1.y = acc[5] * 0.125f + b1.y;
            o1.z = acc[6] * 0.125f + b1.z; o1.w = acc[7] * 0.125f + b1.w;
            *(float4*)(out_f32 + (size_t)w * 32 + c0)     = o0;
            *(float4*)(out_f32 + (size_t)w * 32 + c0 + 4) = o1;
        }
    }
}

// ---------------- launch ------------------------------------------------------
extern "C" void kernel_launch(void* const* d_in, const int* in_sizes, int n_in,
                              void* d_out, int out_size) {
    const float* x   = (const float*)d_in[0];
    const void*  ei  = d_in[1];
    const float* W1  = (const float*)d_in[2];
    const float* at_s1 = (const float*)d_in[3];
    const float* at_d1 = (const float*)d_in[4];
    const float* b1  = (const float*)d_in[5];
    const float* W2  = (const float*)d_in[6];
    const float* at_s2 = (const float*)d_in[7];
    const float* at_d2 = (const float*)d_in[8];
    const float* b2  = (const float*)d_in[9];
    float* out = (float*)d_out;

    float *pas1, *pad1, *pas2, *pad2;
    __half *x16, *w1h, *w2h, *h1a16, *h16;
    cudaGetSymbolAddress((void**)&x16, g_x16);
    cudaGetSymbolAddress((void**)&w1h, g_w1h);
    cudaGetSymbolAddress((void**)&w2h, g_w2h);
    cudaGetSymbolAddress((void**)&h1a16, g_h1a16);
    cudaGetSymbolAddress((void**)&h16, g_h16);
    cudaGetSymbolAddress((void**)&pas1, g_as1);
    cudaGetSymbolAddress((void**)&pad1, g_ad1);
    cudaGetSymbolAddress((void**)&pas2, g_as2);
    cudaGetSymbolAddress((void**)&pad2, g_ad2);

    // CSR build + fp16 conversions (conversions independent of CSR)
    detect64_kernel<<<1, 256>>>((const unsigned int*)ei);
    zero_cnt_kernel<<<(N_NODES + 255) / 256, 256>>>();
    count_kernel<<<(E_TOT + 255) / 256, 256>>>(ei);
    convx_kernel<<<(N_NODES * 32 + 255) / 256, 256>>>(x);
    convw_kernel<<<(12288 + 255) / 256, 256>>>(W1, W2);
    scan1_kernel<<<SCAN_NB, 1024>>>();
    scan2_kernel<<<1, 32>>>();
    scan3_kernel<<<(N_NODES + 255) / 256, 256>>>();
    scatter_kernel<<<(E_TOT + 255) / 256, 256>>>(ei);

    dim3 hg1(128 / HG_BN, N_PAD / HG_BM);   // (2, 391)
    dim3 hg2(256 / HG_BN, N_PAD / HG_BM);   // (4, 391)

    // layer 1
    hgemm_fused_kernel<4><<<hg1, 256>>>(x16, w1h, h16, pas1, pad1, at_s1, at_d1, 128);
    gat_fused_kernel<4, true><<<(N_NODES + 7) / 8, 256>>>(pas1, pad1, b1, nullptr);

    // layer 2
    hgemm_fused_kernel<8><<<hg2, 256>>>(h1a16, w2h, h16, pas2, pad2, at_s2, at_d2, 128);
    gat_fused_kernel<8, false><<<(N_NODES + 7) / 8, 256>>>(pas2, pad2, b2, out);
}

// round 17
// speedup vs baseline: 1.1022x; 1.0532x over previous
#include <cuda_runtime.h>
#include <cuda_fp16.h>
#include <math.h>
#include <mma.h>

using namespace nvcuda;

// Problem constants (fixed by the dataset)
#define N_NODES 50000
#define N_PAD   50048                        // 391 * 128
#define E_EDGES 800000
#define E_TOT   (E_EDGES + N_NODES)
#define SCAN_NB ((N_NODES + 1023) / 1024)   // 49

// ---------------- scratch (static __device__ allocations only) ----------------
__device__ __half g_x16[(size_t)N_PAD * 128];   // fp16 copy of x
__device__ __half g_h1a16[(size_t)N_PAD * 128]; // elu(gat1) fp16 (gemm2 input)
__device__ __half g_h16[(size_t)N_PAD * 256];   // fp16 h (per-layer stride)
__device__ __half g_w1h[128 * 128];
__device__ __half g_w2h[128 * 256];
__device__ float  g_as1[N_NODES * 4];
__device__ float  g_ad1[N_NODES * 4];
__device__ float  g_as2[N_NODES * 8];
__device__ float  g_ad2[N_NODES * 8];
__device__ int    g_cnt[N_NODES];
__device__ int    g_tmp[N_NODES];
__device__ int    g_bsum[SCAN_NB];
__device__ int    g_boff[SCAN_NB];
__device__ int    g_rowptr[N_NODES + 1];
__device__ int    g_cursor[N_NODES];
__device__ int    g_col[E_TOT];
__device__ int    g_is64;

// ---------------- second stream for CSR/GEMM overlap (created pre-main) -------
static cudaStream_t g_s2;
static cudaEvent_t  g_ev1, g_ev2;
struct StreamInit {
    StreamInit() {
        cudaStreamCreateWithFlags(&g_s2, cudaStreamNonBlocking);
        cudaEventCreateWithFlags(&g_ev1, cudaEventDisableTiming);
        cudaEventCreateWithFlags(&g_ev2, cudaEventDisableTiming);
    }
};
static StreamInit g_si;

// ---------------- dtype detection for edge_index (int64 vs int32) -------------
__global__ void detect64_kernel(const unsigned int* __restrict__ w) {
    __shared__ int any;
    if (threadIdx.x == 0) any = 0;
    __syncthreads();
    for (int i = 1 + 2 * threadIdx.x; i < 2048; i += 2 * blockDim.x)
        if (w[i] != 0u) any = 1;   // benign race
    __syncthreads();
    if (threadIdx.x == 0) g_is64 = (any == 0) ? 1 : 0;
}

__global__ void zero_cnt_kernel() {
    int i = blockIdx.x * blockDim.x + threadIdx.x;
    if (i < N_NODES) g_cnt[i] = 0;
}

__global__ void count_kernel(const void* __restrict__ ei) {
    int e = blockIdx.x * blockDim.x + threadIdx.x;
    if (e >= E_TOT) return;
    int dst;
    if (e < E_EDGES) {
        if (g_is64) dst = (int)((const long long*)ei)[(size_t)E_EDGES + e];
        else        dst = ((const int*)ei)[E_EDGES + e];
    } else {
        dst = e - E_EDGES;   // self loop
    }
    atomicAdd(&g_cnt[dst], 1);
}

// ---------------- multi-block scan (3 tiny kernels) ---------------------------
__global__ void scan1_kernel() {
    int b = blockIdx.x, tid = threadIdx.x;
    int i = b * 1024 + tid;
    int lane = tid & 31, wid = tid >> 5;
    int v = (i < N_NODES) ? g_cnt[i] : 0;
    int x = v;
#pragma unroll
    for (int off = 1; off < 32; off <<= 1) {
        int t = __shfl_up_sync(0xffffffffu, x, off);
        if (lane >= off) x += t;
    }
    __shared__ int wsum[32];
    if (lane == 31) wsum[wid] = x;
    __syncthreads();
    if (wid == 0) {
        int y = wsum[lane];
#pragma unroll
        for (int off = 1; off < 32; off <<= 1) {
            int t = __shfl_up_sync(0xffffffffu, y, off);
            if (lane >= off) y += t;
        }
        wsum[lane] = y;
    }
    __syncthreads();
    int incl = x + (wid ? wsum[wid - 1] : 0);
    if (i < N_NODES) g_tmp[i] = incl;
    if (tid == 1023) g_bsum[b] = incl;
}

__global__ void scan2_kernel() {
    if (threadIdx.x == 0) {
        int run = 0;
#pragma unroll 1
        for (int j = 0; j < SCAN_NB; j++) { g_boff[j] = run; run += g_bsum[j]; }
        g_rowptr[0] = 0;
    }
}

__global__ void scan3_kernel() {
    int i = blockIdx.x * blockDim.x + threadIdx.x;
    if (i >= N_NODES) return;
    int incl = g_tmp[i] + g_boff[i >> 10];
    g_rowptr[i + 1] = incl;
    g_cursor[i]     = incl - g_cnt[i];
}

__global__ void scatter_kernel(const void* __restrict__ ei) {
    int e = blockIdx.x * blockDim.x + threadIdx.x;
    if (e >= E_TOT) return;
    int src, dst;
    if (e < E_EDGES) {
        if (g_is64) {
            const long long* p = (const long long*)ei;
            src = (int)p[e];
            dst = (int)p[(size_t)E_EDGES + e];
        } else {
            const int* p = (const int*)ei;
            src = p[e];
            dst = p[E_EDGES + e];
        }
    } else {
        src = dst = e - E_EDGES;
    }
    int pos = atomicAdd(&g_cursor[dst], 1);
    g_col[pos] = src;
}

// ---------------- fp32 -> fp16 conversions (x + W1 + W2, one kernel) ----------
#define NX4 (N_NODES * 32)       // float4 count for x
__global__ void conv_kernel(const float* __restrict__ x,
                            const float* __restrict__ W1,
                            const float* __restrict__ W2) {
    int i = blockIdx.x * blockDim.x + threadIdx.x;
    if (i < NX4) {
        float4 v = ((const float4*)x)[i];
        ((__half2*)g_x16)[2 * i]     = __floats2half2_rn(v.x, v.y);
        ((__half2*)g_x16)[2 * i + 1] = __floats2half2_rn(v.z, v.w);
    } else if (i < NX4 + 4096) {
        int j = i - NX4;
        float4 v = ((const float4*)W1)[j];
        ((__half2*)g_w1h)[2 * j]     = __floats2half2_rn(v.x, v.y);
        ((__half2*)g_w1h)[2 * j + 1] = __floats2half2_rn(v.z, v.w);
    } else if (i < NX4 + 4096 + 8192) {
        int j = i - NX4 - 4096;
        float4 v = ((const float4*)W2)[j];
        ((__half2*)g_w2h)[2 * j]     = __floats2half2_rn(v.x, v.y);
        ((__half2*)g_w2h)[2 * j + 1] = __floats2half2_rn(v.z, v.w);
    }
}

// ------- fp16 tensor-core GEMM with fused alpha + fp16-store epilogue ---------
#define HG_BM 128
#define HG_BN 64
#define HG_BK 32
#define HLDA 40
#define HLDB 72
#define CT_LD 72   // fp32 epilogue tile leading dim

#define SMEM_BYTES (HG_BM * CT_LD * 4)   // 36864 > Ah+Bh bytes (14848)

template <int H>
__global__ void hgemm_fused_kernel(const __half* __restrict__ A,
                                   const __half* __restrict__ Bw,
                                   __half* __restrict__ H16,
                                   float* __restrict__ as_out,
                                   float* __restrict__ ad_out,
                                   const float* __restrict__ att_s,
                                   const float* __restrict__ att_d,
                                   int K) {
    constexpr int N = H * 32;
    __shared__ __align__(16) char smraw[SMEM_BYTES];
    __half* Ah = (__half*)smraw;
    __half* Bh = (__half*)(smraw + HG_BM * HLDA * 2);
    float*  Ct = (float*)smraw;

    int tid = threadIdx.x;
    int wid = tid >> 5;
    int wm = wid & 3, wn = wid >> 2;
    size_t row0 = (size_t)blockIdx.y * HG_BM;
    int col0 = blockIdx.x * HG_BN;

    wmma::fragment<wmma::accumulator, 16, 16, 16, float> c[2][2];
#pragma unroll
    for (int i = 0; i < 2; i++)
#pragma unroll
        for (int j = 0; j < 2; j++) wmma::fill_fragment(c[i][j], 0.f);

    for (int k0 = 0; k0 < K; k0 += HG_BK) {
#pragma unroll
        for (int i = 0; i < 2; i++) {
            int f = tid + i * 256;
            int r = f >> 2, cc = (f & 3) * 8;
            *(uint4*)(Ah + r * HLDA + cc) =
                *(const uint4*)(A + (row0 + r) * K + k0 + cc);
        }
        {
            int r = tid >> 3, cc = (tid & 7) * 8;
            *(uint4*)(Bh + r * HLDB + cc) =
                *(const uint4*)(Bw + (size_t)(k0 + r) * N + col0 + cc);
        }
        __syncthreads();
#pragma unroll
        for (int kk = 0; kk < HG_BK; kk += 16) {
            wmma::fragment<wmma::matrix_a, 16, 16, 16, __half, wmma::row_major> a[2];
            wmma::fragment<wmma::matrix_b, 16, 16, 16, __half, wmma::row_major> b[2];
#pragma unroll
            for (int mi = 0; mi < 2; mi++)
                wmma::load_matrix_sync(a[mi], Ah + (wm * 32 + mi * 16) * HLDA + kk, HLDA);
#pragma unroll
            for (int ni = 0; ni < 2; ni++)
                wmma::load_matrix_sync(b[ni], Bh + kk * HLDB + wn * 32 + ni * 16, HLDB);
#pragma unroll
            for (int mi = 0; mi < 2; mi++)
#pragma unroll
                for (int ni = 0; ni < 2; ni++)
                    wmma::mma_sync(c[mi][ni], a[mi], b[ni], c[mi][ni]);
        }
        __syncthreads();
    }

    // epilogue: spill fp32 tile to smem (operand buffers are dead now)
#pragma unroll
    for (int mi = 0; mi < 2; mi++)
#pragma unroll
        for (int ni = 0; ni < 2; ni++)
            wmma::store_matrix_sync(
                Ct + (wm * 32 + mi * 16) * CT_LD + wn * 32 + ni * 16,
                c[mi][ni], CT_LD, wmma::mem_row_major);
    __syncthreads();

    // each thread owns one (row, 32-col head slice): dots + fp16 store
    int row = tid >> 1;
    int seg = tid & 1;
    size_t node = row0 + row;
    int head = (col0 >> 5) + seg;
    const float* Crow = Ct + row * CT_LD + seg * 32;
    const float* a1 = att_s + head * 32;
    const float* a2 = att_d + head * 32;

    float s1 = 0.f, s2 = 0.f;
    __half hv[32];
#pragma unroll
    for (int j = 0; j < 32; j += 4) {
        float4 v  = *(const float4*)(Crow + j);
        float4 w1 = *(const float4*)(a1 + j);
        float4 w2 = *(const float4*)(a2 + j);
        s1 += v.x * w1.x + v.y * w1.y + v.z * w1.z + v.w * w1.w;
        s2 += v.x * w2.x + v.y * w2.y + v.z * w2.z + v.w * w2.w;
        *(__half2*)(hv + j)     = __floats2half2_rn(v.x, v.y);
        *(__half2*)(hv + j + 2) = __floats2half2_rn(v.z, v.w);
    }
    __half* hp = H16 + node * N + col0 + seg * 32;
#pragma unroll
    for (int j = 0; j < 4; j++)
        ((uint4*)hp)[j] = ((uint4*)hv)[j];
    if (node < N_NODES) {
        as_out[node * H + head] = s1;
        ad_out[node * H + head] = s2;
    }
}

// ------- fused stats + aggregation: one warp per destination node -------------
template <int H, bool ELU_FP16_OUT>
__global__ void gat_fused_kernel(const float* __restrict__ asrc,
                                 const float* __restrict__ adst,
                                 const float* __restrict__ bias,
                                 float* __restrict__ out_f32) {
    __shared__ float wsm_all[8][32 * H];     // 8 warps/block
    int wslot = threadIdx.x >> 5;
    float* wsm = wsm_all[wslot];

    int w    = (blockIdx.x * blockDim.x + threadIdx.x) >> 5;
    int lane = threadIdx.x & 31;
    if (w >= N_NODES) return;
    int beg = g_rowptr[w], end = g_rowptr[w + 1];

    float ad[H];
#pragma unroll
    for (int h = 0; h < H; h++) ad[h] = adst[(size_t)w * H + h];

    // ---- pass A: online max+sum, lane-parallel ----
    float m[H], s[H];
#pragma unroll
    for (int h = 0; h < H; h++) { m[h] = -1e30f; s[h] = 0.f; }
    for (int e = beg + lane; e < end; e += 32) {
        int src = g_col[e];
        const float4* ap4 = (const float4*)(asrc + (size_t)src * H);
        float av[H];
#pragma unroll
        for (int q = 0; q < H / 4; q++) {
            float4 t = ap4[q];
            av[4 * q] = t.x; av[4 * q + 1] = t.y; av[4 * q + 2] = t.z; av[4 * q + 3] = t.w;
        }
#pragma unroll
        for (int h = 0; h < H; h++) {
            float x = av[h] + ad[h];
            x = x > 0.f ? x : 0.2f * x;
            if (x > m[h]) {
                s[h] = s[h] * __expf(m[h] - x) + 1.f;
                m[h] = x;
            } else {
                s[h] += __expf(x - m[h]);
            }
        }
    }
#pragma unroll
    for (int h = 0; h < H; h++) {
        float mw = m[h];
#pragma unroll
        for (int off = 16; off; off >>= 1)
            mw = fmaxf(mw, __shfl_xor_sync(0xffffffffu, mw, off));
        float sw = s[h] * __expf(m[h] - mw);
#pragma unroll
        for (int off = 16; off; off >>= 1)
            sw += __shfl_xor_sync(0xffffffffu, sw, off);
        m[h] = mw;
        s[h] = 1.f / sw;     // inv_s
    }

    // ---- pass B: chunked weight staging + accumulate ----
    constexpr int CH = (H == 4) ? 4 : 8;     // channels per lane
    int hsel = (H == 4) ? (lane >> 3) : (lane >> 2);
    float acc[CH];
#pragma unroll
    for (int j = 0; j < CH; j++) acc[j] = 0.f;

    for (int c0 = beg; c0 < end; c0 += 32) {
        int ne = min(32, end - c0);
        int mysrc = 0;
        if (lane < ne) {
            int e = c0 + lane;
            mysrc = g_col[e];                 // coalesced
            const float4* ap4 = (const float4*)(asrc + (size_t)mysrc * H);
            float av[H];
#pragma unroll
            for (int q = 0; q < H / 4; q++) {
                float4 t = ap4[q];
                av[4 * q] = t.x; av[4 * q + 1] = t.y; av[4 * q + 2] = t.z; av[4 * q + 3] = t.w;
            }
#pragma unroll
            for (int h = 0; h < H; h++) {
                float x = av[h] + ad[h];
                x = x > 0.f ? x : 0.2f * x;
                wsm[lane * H + h] = __expf(x - m[h]) * s[h];
            }
        }
        __syncwarp();
        for (int i = 0; i < ne; i++) {
            int src_i = __shfl_sync(0xffffffffu, mysrc, i);
            float wt = wsm[i * H + hsel];     // LDS broadcast within head group
            if (H == 4) {
                uint2 hv = *((const uint2*)(g_h16 + (size_t)src_i * 128) + lane);
                float2 f0 = __half22float2(*(__half2*)&hv.x);
                float2 f1 = __half22float2(*(__half2*)&hv.y);
                acc[0] += f0.x * wt;
                acc[1] += f0.y * wt;
                acc[2] += f1.x * wt;
                acc[3] += f1.y * wt;
            } else {
                uint4 hv = *((const uint4*)(g_h16 + (size_t)src_i * 256) + lane);
                float2 f0 = __half22float2(*(__half2*)&hv.x);
                float2 f1 = __half22float2(*(__half2*)&hv.y);
                float2 f2 = __half22float2(*(__half2*)&hv.z);
                float2 f3 = __half22float2(*(__half2*)&hv.w);
                acc[0] += f0.x * wt; acc[1] += f0.y * wt;
                acc[2] += f1.x * wt; acc[3] += f1.y * wt;
                acc[4] += f2.x * wt; acc[5] += f2.y * wt;
                acc[6] += f3.x * wt; acc[7] += f3.y * wt;
            }
        }
        __syncwarp();
    }

    if (ELU_FP16_OUT) {
        // layer 1: concat + bias + ELU, fp16 store to g_h1a16
        float4 bv = *((const float4*)bias + lane);
        float4 o;
        o.x = acc[0] + bv.x; o.y = acc[1] + bv.y; o.z = acc[2] + bv.z; o.w = acc[3] + bv.w;
        o.x = o.x > 0.f ? o.x : expm1f(o.x);
        o.y = o.y > 0.f ? o.y : expm1f(o.y);
        o.z = o.z > 0.f ? o.z : expm1f(o.z);
        o.w = o.w > 0.f ? o.w : expm1f(o.w);
        uint2 o16;
        *(__half2*)&o16.x = __floats2half2_rn(o.x, o.y);
        *(__half2*)&o16.y = __floats2half2_rn(o.z, o.w);
        ((uint2*)(g_h1a16 + (size_t)w * 128))[lane] = o16;
    } else {
        // layer 2: head-mean + bias, fp32 store to out
#pragma unroll
        for (int off = 4; off < 32; off <<= 1)
#pragma unroll
            for (int j = 0; j < CH; j++)
                acc[j] += __shfl_xor_sync(0xffffffffu, acc[j], off);
        if (lane < 4) {
            int c0 = lane * 8;
            float4 b0 = *(const float4*)(bias + c0);
            float4 b1 = *(const float4*)(bias + c0 + 4);
            float4 o0, o1;
            o0.x = acc[0] * 0.125f + b0.x; o0.y = acc[1] * 0.125f + b0.y;
            o0.z = acc[2] * 0.125f + b0.z; o0.w = acc[3] * 0.125f + b0.w;
            o1.x = acc[4] * 0.125f + b1.x; o1.y = acc[5] * 0.125f + b1.y;
            o1.z = acc[6] * 0.125f + b1.z; o1.w = acc[7] * 0.125f + b1.w;
            *(float4*)(out_f32 + (size_t)w * 32 + c0)     = o0;
            *(float4*)(out_f32 + (size_t)w * 32 + c0 + 4) = o1;
        }
    }
}

// ---------------- launch ------------------------------------------------------
extern "C" void kernel_launch(void* const* d_in, const int* in_sizes, int n_in,
                              void* d_out, int out_size) {
    const float* x   = (const float*)d_in[0];
    const void*  ei  = d_in[1];
    const float* W1  = (const float*)d_in[2];
    const float* at_s1 = (const float*)d_in[3];
    const float* at_d1 = (const float*)d_in[4];
    const float* b1  = (const float*)d_in[5];
    const float* W2  = (const float*)d_in[6];
    const float* at_s2 = (const float*)d_in[7];
    const float* at_d2 = (const float*)d_in[8];
    const float* b2  = (const float*)d_in[9];
    float* out = (float*)d_out;

    float *pas1, *pad1, *pas2, *pad2;
    __half *x16, *w1h, *w2h, *h1a16, *h16;
    cudaGetSymbolAddress((void**)&x16, g_x16);
    cudaGetSymbolAddress((void**)&w1h, g_w1h);
    cudaGetSymbolAddress((void**)&w2h, g_w2h);
    cudaGetSymbolAddress((void**)&h1a16, g_h1a16);
    cudaGetSymbolAddress((void**)&h16, g_h16);
    cudaGetSymbolAddress((void**)&pas1, g_as1);
    cudaGetSymbolAddress((void**)&pad1, g_ad1);
    cudaGetSymbolAddress((void**)&pas2, g_as2);
    cudaGetSymbolAddress((void**)&pad2, g_ad2);

    dim3 hg1(128 / HG_BN, N_PAD / HG_BM);   // (2, 391)
    dim3 hg2(256 / HG_BN, N_PAD / HG_BM);   // (4, 391)

    // fork: CSR chain on g_s2, conv + gemm1 on main stream
    cudaEventRecord(g_ev1, 0);
    cudaStreamWaitEvent(g_s2, g_ev1, 0);

    // --- stream s2: CSR build ---
    detect64_kernel<<<1, 256, 0, g_s2>>>((const unsigned int*)ei);
    zero_cnt_kernel<<<(N_NODES + 255) / 256, 256, 0, g_s2>>>();
    count_kernel<<<(E_TOT + 255) / 256, 256, 0, g_s2>>>(ei);
    scan1_kernel<<<SCAN_NB, 1024, 0, g_s2>>>();
    scan2_kernel<<<1, 32, 0, g_s2>>>();
    scan3_kernel<<<(N_NODES + 255) / 256, 256, 0, g_s2>>>();
    scatter_kernel<<<(E_TOT + 255) / 256, 256, 0, g_s2>>>(ei);

    // --- main stream: fp16 conversions + gemm1 (independent of CSR) ---
    conv_kernel<<<(NX4 + 12288 + 255) / 256, 256>>>(x, W1, W2);
    hgemm_fused_kernel<4><<<hg1, 256>>>(x16, w1h, h16, pas1, pad1, at_s1, at_d1, 128);

    // join: gat1 needs both CSR and gemm1 results
    cudaEventRecord(g_ev2, g_s2);
    cudaStreamWaitEvent(0, g_ev2, 0);

    // layer 1 aggregation
    gat_fused_kernel<4, true><<<(N_NODES + 7) / 8, 256>>>(pas1, pad1, b1, nullptr);

    // layer 2
    hgemm_fused_kernel<8><<<hg2, 256>>>(h1a16, w2h, h16, pas2, pad2, at_s2, at_d2, 128);
    gat_fused_kernel<8, false><<<(N_NODES + 7) / 8, 256>>>(pas2, pad2, b2, out);
}